// round 9
// baseline (speedup 1.0000x reference)
#include <cuda_runtime.h>
#include <cstdint>

#define L      2048
#define C_IN   16
#define GROUPS 4
#define NEG_INF -1000000000.0f
#define SLOT   32          // fixed padded slots per (ch,row); overflow -> g_list

// Padded fast-path lists: SLOT entries per (ch,row), column-sorted, padded
// with sentinel col = INT_MAX. Always fully written for every row.
__device__ float2 g_slot[(size_t)C_IN * L * SLOT];
// Packed 16-bit columns of the same lists: 32 cols -> 4 uint4 per (ch,row).
// Sentinel 0x7FFF for unused slots. Lets k2 range-scan with 4 LDG.128.
__device__ uint4  g_colpack[(size_t)C_IN * L * 4];
// Full-stride overflow lists (correctness fallback when support > SLOT).
__device__ float2 g_list[(size_t)C_IN * L * L];
__device__ int    g_cnt[C_IN * L];

// ---------------------------------------------------------------------------
// Kernel 1: row-wise sparsemax (causal) -> sorted compressed nonzero list.
// One block (128 thr) per (channel,row); thread t owns cols [16t,16t+16).
// tau0 = rowmax-1 bounds the support; survivors of tau0 are compacted to smem
// (sorted), then WARP 0 ALONE finishes Michelot + the final writes.
// ---------------------------------------------------------------------------
__global__ __launch_bounds__(128) void sparsemax_kernel(const float* __restrict__ scores)
{
    const int row  = blockIdx.x;
    const int ch   = blockIdx.y;
    const int tid  = threadIdx.x;
    const int lane = tid & 31;
    const int warp = tid >> 5;            // 4 warps
    const size_t base = ((size_t)ch * L + row) * (size_t)L;
    const int j0  = tid * 16;
    const int rem = row - j0;             // valid elements: x <= rem

    float z[16];
    if (rem >= 15) {
#pragma unroll
        for (int q = 0; q < 4; q++) {
            const float4 a = *reinterpret_cast<const float4*>(scores + base + j0 + 4 * q);
            z[4*q+0]=a.x; z[4*q+1]=a.y; z[4*q+2]=a.z; z[4*q+3]=a.w;
        }
    } else {
#pragma unroll
        for (int x = 0; x < 16; x++)
            z[x] = (x <= rem) ? scores[base + j0 + x] : NEG_INF;
    }

    __shared__ float  smax[4];
    __shared__ int    swtot[4];
    __shared__ int    s_col[SLOT];        // final columns (warp 0 phase)
    __shared__ float2 slist[2048];        // survivors of tau0 (capacity-proof)

    // ---- row max ----
    float m = z[0];
#pragma unroll
    for (int k = 1; k < 16; k++) m = fmaxf(m, z[k]);
#pragma unroll
    for (int o = 16; o > 0; o >>= 1) m = fmaxf(m, __shfl_xor_sync(0xffffffffu, m, o));
    if (lane == 0) smax[warp] = m;
    __syncthreads();                                           // (1)
    const float tau0 = fmaxf(fmaxf(smax[0], smax[1]), fmaxf(smax[2], smax[3])) - 1.0f;

    // ---- compact survivors of tau0 into smem, column-sorted ----
    unsigned nz = 0u;
#pragma unroll
    for (int x = 0; x < 16; x++)
        if (z[x] > tau0) nz |= (1u << x);
    const int tcnt = __popc(nz);

    int v = tcnt;                          // warp inclusive scan
#pragma unroll
    for (int o = 1; o < 32; o <<= 1) {
        const int n = __shfl_up_sync(0xffffffffu, v, o);
        if (lane >= o) v += n;
    }
    const int toff = v - tcnt;
    if (lane == 31) swtot[warp] = v;
    __syncthreads();                                           // (2)
    int wbase = 0;
#pragma unroll
    for (int w = 0; w < 4; w++)
        if (w < warp) wbase += swtot[w];
    int pos = wbase + toff;
#pragma unroll
    for (int x = 0; x < 16; x++) {
        if ((nz >> x) & 1u) {
            slist[pos] = make_float2(__int_as_float(j0 + x), z[x]);
            pos++;
        }
    }
    __syncthreads();                                           // (3)
    if (warp != 0) return;                 // warps 1-3 done

    // ---- warp 0: Michelot on the small smem list (shfl-only) ----
    const int total = swtot[0] + swtot[1] + swtot[2] + swtot[3];
    float tau = tau0;
    int prev = -1;
    for (int it = 0; it < 32; it++) {
        float S = 0.0f, C = 0.0f;
        for (int n = lane; n < total; n += 32) {
            const float y = slist[n].y;
            if (y > tau) { S += y; C += 1.0f; }
        }
#pragma unroll
        for (int o = 16; o > 0; o >>= 1) {
            S += __shfl_xor_sync(0xffffffffu, S, o);
            C += __shfl_xor_sync(0xffffffffu, C, o);
        }
        const int ci = (int)C;             // >=1 always (argmax survives)
        tau = (S - 1.0f) / C;
        if (ci == prev) break;             // support stable -> converged
        prev = ci;
    }

    // ---- final order-preserving compaction: slots + packed cols ----
    s_col[lane] = 0x7FFF;                  // sentinel default
    __syncwarp();
    float2* slot = g_slot + (size_t)(ch * L + row) * SLOT;
    float2* lst  = g_list + base;
    int opos = 0;
    for (int n0 = 0; n0 < total; n0 += 32) {
        const int n = n0 + lane;
        float2 e; bool keep = false;
        if (n < total) { e = slist[n]; keep = (e.y > tau); }
        const unsigned b = __ballot_sync(0xffffffffu, keep);
        if (keep) {
            const int k = opos + __popc(b & ((1u << lane) - 1u));
            const float2 w = make_float2(e.x, e.y - tau);
            if (k < SLOT) { slot[k] = w; s_col[k] = __float_as_int(e.x); }
            lst[k] = w;                    // overflow-safe full copy (tiny)
        }
        opos += __popc(b);
    }
    // sentinel-pad remaining slots (col = INT_MAX)
    for (int n = opos + lane; n < SLOT; n += 32)
        slot[n] = make_float2(__int_as_float(0x7FFFFFFF), 0.0f);
    __syncwarp();
    // pack 32 cols into 16 uint32 (two int16 each) = 4 uint4
    if (lane < 16) {
        const unsigned pk = (unsigned)(s_col[2 * lane] & 0xFFFF)
                          | ((unsigned)(s_col[2 * lane + 1] & 0xFFFF) << 16);
        reinterpret_cast<unsigned*>(g_colpack + (size_t)(ch * L + row) * 4)[lane] = pk;
    }
    if (lane == 0) g_cnt[ch * L + row] = opos;
}

// ---------------------------------------------------------------------------
// Kernel 2: grouped 3x3 conv from SORTED sparse lists + bias + causal zero.
// One block (256 thr) per (out-row i, group g). Warp w covers cols [256w,256w+256).
// 96 threads precompute per-(list,warp) [start,end) ranges by scanning the
// PACKED 16-bit columns with 4 LDG.128 (broadcast across the 8-lane group).
// ---------------------------------------------------------------------------
__global__ __launch_bounds__(256) void conv_sparse_kernel(const float* __restrict__ weight,
                                                          const float* __restrict__ bias,
                                                          float* __restrict__ out)
{
    __shared__ float wsm[144];       // [4 oc][4 ic][3][3]
    __shared__ float bsm[4];
    __shared__ int   scnt_s[12];
    __shared__ int2  srange[12][8];  // [list p = icc*3+dr][warp]

    const int i    = blockIdx.x;     // output row
    const int g    = blockIdx.y;     // group
    const int tid  = threadIdx.x;
    const int warp = tid >> 5;
    const int j0   = tid * 8;

    if (tid < 144) wsm[tid] = weight[g * 144 + tid];
    if (tid < 4)   bsm[tid] = bias[g * 4 + tid];

    // ---- per-(list,warp) ranges: packed-column scan, 4 LDG.128 ----
    if (tid < 96) {
        const int p   = tid >> 3;          // 0..11
        const int w   = tid & 7;           // warp
        const int icc = p / 3;
        const int dr  = p - icc * 3;
        const int r   = i + dr - 1;
        int s = 0, e = 0, c = 0;
        if (r >= 0 && r < L) {
            const int gc = g * 4 + icc;
            c = g_cnt[gc * L + r];
            const int lo = w * 256 - 1;
            const int hi = w * 256 + 256;
            const uint4* pk = g_colpack + (size_t)(gc * L + r) * 4;
#pragma unroll
            for (int q = 0; q < 4; q++) {
                const uint4 u = __ldg(&pk[q]);
                const unsigned uu[4] = {u.x, u.y, u.z, u.w};
#pragma unroll
                for (int h = 0; h < 4; h++) {
                    const int c0 = (int)(uu[h] & 0xFFFFu);   // sentinel 0x7FFF > hi
                    const int c1 = (int)(uu[h] >> 16);
                    s += (c0 < lo) + (c1 < lo);
                    e += (c0 <= hi) + (c1 <= hi);
                }
            }
            if (c > SLOT) {                        // rare correctness fallback
                const float2* lst = g_list + ((size_t)gc * L + r) * (size_t)L;
                s = 0; e = 0;
                for (int n = 0; n < c; n++) {
                    const int col = __float_as_int(lst[n].x);
                    s += (col < lo);
                    e += (col <= hi);
                }
            }
        }
        if (w == 0) scnt_s[p] = c;
        srange[p][w] = make_int2(s, e);
    }
    __syncthreads();

    // ---- threads fully above the diagonal: zero-store and exit ----
    if (j0 > i) {
        const float4 zq = make_float4(0.f, 0.f, 0.f, 0.f);
#pragma unroll
        for (int o = 0; o < 4; o++) {
            float* ob = out + ((size_t)(g * 4 + o) * L + i) * (size_t)L + j0;
            *reinterpret_cast<float4*>(ob)     = zq;
            *reinterpret_cast<float4*>(ob + 4) = zq;
        }
        return;
    }

    float acc[4][8];
#pragma unroll
    for (int o = 0; o < 4; o++)
#pragma unroll
        for (int x = 0; x < 8; x++) acc[o][x] = 0.0f;

#pragma unroll
    for (int p = 0; p < 12; p++) {
        const int icc = p / 3;
        const int dr  = p - icc * 3;
        const int r   = i + dr - 1;
        if (r < 0 || r >= L) continue;
        const int2 se = srange[p][warp];
        if (se.x >= se.y) continue;
        const int gc = g * 4 + icc;
        const int c  = scnt_s[p];
        const float2* lp = (c <= SLOT)
            ? g_slot + (size_t)(gc * L + r) * SLOT
            : g_list + ((size_t)gc * L + r) * (size_t)L;
        for (int n = se.x; n < se.y; n++) {      // ~1-2 entries, warp-uniform
            const float2 e = __ldg(&lp[n]);      // broadcast load (L1 hot)
            const int rel = __float_as_int(e.x) - j0 + 1;   // tap center, 0..9 valid
            if ((unsigned)rel > 9u) continue;
            const float v = e.y;
#pragma unroll
            for (int x = 0; x < 8; x++) {
                const int dc = rel - x;          // kernel col tap
                if ((unsigned)dc < 3u) {
#pragma unroll
                    for (int o = 0; o < 4; o++)
                        acc[o][x] = fmaf(wsm[((o * 4 + icc) * 3 + dr) * 3 + dc], v, acc[o][x]);
                }
            }
        }
    }

    // ---- bias + causal mask + dense store ----
#pragma unroll
    for (int o = 0; o < 4; o++) {
        const float b = bsm[o];
        float vv[8];
#pragma unroll
        for (int x = 0; x < 8; x++)
            vv[x] = (j0 + x <= i) ? (acc[o][x] + b) : 0.0f;
        float4 v0, v1;
        v0.x=vv[0]; v0.y=vv[1]; v0.z=vv[2]; v0.w=vv[3];
        v1.x=vv[4]; v1.y=vv[5]; v1.z=vv[6]; v1.w=vv[7];
        float* ob = out + ((size_t)(g * 4 + o) * L + i) * (size_t)L + j0;
        *reinterpret_cast<float4*>(ob)     = v0;
        *reinterpret_cast<float4*>(ob + 4) = v1;
    }
}

// ---------------------------------------------------------------------------
extern "C" void kernel_launch(void* const* d_in, const int* in_sizes, int n_in,
                              void* d_out, int out_size)
{
    const float* scores = (const float*)d_in[0];
    const float* weight = (const float*)d_in[1];
    const float* bias   = (const float*)d_in[2];
    float* out = (float*)d_out;

    sparsemax_kernel<<<dim3(L, C_IN), 128>>>(scores);
    conv_sparse_kernel<<<dim3(L, GROUPS), 256>>>(weight, bias, out);
}

// round 10
// speedup vs baseline: 1.0326x; 1.0326x over previous
#include <cuda_runtime.h>
#include <cstdint>

#define L      2048
#define C_IN   16
#define GROUPS 4
#define NEG_INF -1000000000.0f
#define SLOT   32          // fixed padded slots per (ch,row); overflow -> g_list
#define SENT   0x7FFFFFFF

// Padded fast-path lists: SLOT entries per (ch,row), column-sorted, padded
// with sentinel col = INT_MAX. Always fully written for every row.
__device__ float2 g_slot[(size_t)C_IN * L * SLOT];
// Full-stride overflow lists (correctness fallback when support > SLOT).
__device__ float2 g_list[(size_t)C_IN * L * L];
__device__ int    g_cnt[C_IN * L];

// ---------------------------------------------------------------------------
// Kernel 1: row-wise sparsemax (causal) -> sorted compressed nonzero list.
// One block (128 thr) per (channel,row); thread t owns cols [16t,16t+16).
// tau0 = rowmax-1 bounds the support; survivors of tau0 are compacted to smem
// (sorted), then WARP 0 ALONE finishes Michelot + the final writes.
// ---------------------------------------------------------------------------
__global__ __launch_bounds__(128) void sparsemax_kernel(const float* __restrict__ scores)
{
    const int row  = blockIdx.x;
    const int ch   = blockIdx.y;
    const int tid  = threadIdx.x;
    const int lane = tid & 31;
    const int warp = tid >> 5;            // 4 warps
    const size_t base = ((size_t)ch * L + row) * (size_t)L;
    const int j0  = tid * 16;
    const int rem = row - j0;             // valid elements: x <= rem

    float z[16];
    if (rem >= 15) {
#pragma unroll
        for (int q = 0; q < 4; q++) {
            const float4 a = *reinterpret_cast<const float4*>(scores + base + j0 + 4 * q);
            z[4*q+0]=a.x; z[4*q+1]=a.y; z[4*q+2]=a.z; z[4*q+3]=a.w;
        }
    } else {
#pragma unroll
        for (int x = 0; x < 16; x++)
            z[x] = (x <= rem) ? scores[base + j0 + x] : NEG_INF;
    }

    __shared__ float  smax[4];
    __shared__ int    swtot[4];
    __shared__ float2 slist[2048];        // survivors of tau0 (capacity-proof)

    // ---- row max ----
    float m = z[0];
#pragma unroll
    for (int k = 1; k < 16; k++) m = fmaxf(m, z[k]);
#pragma unroll
    for (int o = 16; o > 0; o >>= 1) m = fmaxf(m, __shfl_xor_sync(0xffffffffu, m, o));
    if (lane == 0) smax[warp] = m;
    __syncthreads();                                           // (1)
    const float tau0 = fmaxf(fmaxf(smax[0], smax[1]), fmaxf(smax[2], smax[3])) - 1.0f;

    // ---- compact survivors of tau0 into smem, column-sorted ----
    unsigned nz = 0u;
#pragma unroll
    for (int x = 0; x < 16; x++)
        if (z[x] > tau0) nz |= (1u << x);
    const int tcnt = __popc(nz);

    int v = tcnt;                          // warp inclusive scan
#pragma unroll
    for (int o = 1; o < 32; o <<= 1) {
        const int n = __shfl_up_sync(0xffffffffu, v, o);
        if (lane >= o) v += n;
    }
    const int toff = v - tcnt;
    if (lane == 31) swtot[warp] = v;
    __syncthreads();                                           // (2)
    int wbase = 0;
#pragma unroll
    for (int w = 0; w < 4; w++)
        if (w < warp) wbase += swtot[w];
    int pos = wbase + toff;
#pragma unroll
    for (int x = 0; x < 16; x++) {
        if ((nz >> x) & 1u) {
            slist[pos] = make_float2(__int_as_float(j0 + x), z[x]);
            pos++;
        }
    }
    __syncthreads();                                           // (3)
    if (warp != 0) return;                 // warps 1-3 done

    // ---- warp 0: Michelot on the small smem list (shfl-only) ----
    const int total = swtot[0] + swtot[1] + swtot[2] + swtot[3];
    float tau = tau0;
    int prev = -1;
    for (int it = 0; it < 32; it++) {
        float S = 0.0f, C = 0.0f;
        for (int n = lane; n < total; n += 32) {
            const float y = slist[n].y;
            if (y > tau) { S += y; C += 1.0f; }
        }
#pragma unroll
        for (int o = 16; o > 0; o >>= 1) {
            S += __shfl_xor_sync(0xffffffffu, S, o);
            C += __shfl_xor_sync(0xffffffffu, C, o);
        }
        const int ci = (int)C;             // >=1 always (argmax survives)
        tau = (S - 1.0f) / C;
        if (ci == prev) break;             // support stable -> converged
        prev = ci;
    }

    // ---- final order-preserving compaction: slots (+ overflow list) ----
    float2* slot = g_slot + (size_t)(ch * L + row) * SLOT;
    float2* lst  = g_list + base;
    int opos = 0;
    for (int n0 = 0; n0 < total; n0 += 32) {
        const int n = n0 + lane;
        float2 e; bool keep = false;
        if (n < total) { e = slist[n]; keep = (e.y > tau); }
        const unsigned b = __ballot_sync(0xffffffffu, keep);
        if (keep) {
            const int k = opos + __popc(b & ((1u << lane) - 1u));
            const float2 w = make_float2(e.x, e.y - tau);
            if (k < SLOT) slot[k] = w;
            lst[k] = w;                    // overflow-safe full copy (tiny)
        }
        opos += __popc(b);
    }
    // sentinel-pad remaining slots (col = INT_MAX)
    for (int n = opos + lane; n < SLOT; n += 32)
        slot[n] = make_float2(__int_as_float(SENT), 0.0f);
    if (lane == 0) g_cnt[ch * L + row] = opos;
}

// ---------------------------------------------------------------------------
// Kernel 2: grouped 3x3 conv from sentinel-padded sorted lists.
// One block (256 thr) per (out-row i, group g). Warp w owns cols [256w,256w+256).
// NO range scan: lane n coalesced-loads slot entry n for each of the 12 lists
// (all 12 LDGs in flight before the single weights barrier), then a
// ballot+shfl loop applies the ~1-2 in-window entries per list.
// ---------------------------------------------------------------------------
__global__ __launch_bounds__(256) void conv_sparse_kernel(const float* __restrict__ weight,
                                                          const float* __restrict__ bias,
                                                          float* __restrict__ out)
{
    __shared__ float wsm[144];       // [4 oc][4 ic][3][3]
    __shared__ float bsm[4];

    const int i    = blockIdx.x;     // output row
    const int g    = blockIdx.y;     // group
    const int tid  = threadIdx.x;
    const int warp = tid >> 5;
    const int lane = tid & 31;
    const int j0   = tid * 8;

    if (tid < 144) wsm[tid] = weight[g * 144 + tid];
    if (tid < 4)   bsm[tid] = bias[g * 4 + tid];

    const bool wzero = (warp * 256 > i);   // warp-uniform: all 256 cols masked

    // ---- issue all 12 list-entry loads (lane n = entry n), pre-barrier ----
    int   ecol[12];
    float eval[12];
    if (!wzero) {
#pragma unroll
        for (int p = 0; p < 12; p++) {
            const int icc = p / 3;
            const int dr  = p - icc * 3;
            const int r   = i + dr - 1;
            ecol[p] = SENT; eval[p] = 0.0f;
            if (r >= 0 && r < L) {
                const float2 e = __ldg(&g_slot[(size_t)((g * 4 + icc) * L + r) * SLOT + lane]);
                ecol[p] = __float_as_int(e.x);
                eval[p] = e.y;
            }
        }
    }
    __syncthreads();                       // weights ready

    if (wzero) {                           // pure zero stores, no other deps
        const float4 zq = make_float4(0.f, 0.f, 0.f, 0.f);
#pragma unroll
        for (int o = 0; o < 4; o++) {
            float* ob = out + ((size_t)(g * 4 + o) * L + i) * (size_t)L + j0;
            *reinterpret_cast<float4*>(ob)     = zq;
            *reinterpret_cast<float4*>(ob + 4) = zq;
        }
        return;
    }

    const int wlo = warp * 256 - 1;
    const int whi = warp * 256 + 256;

    float acc[4][8];
#pragma unroll
    for (int o = 0; o < 4; o++)
#pragma unroll
        for (int x = 0; x < 8; x++) acc[o][x] = 0.0f;

#pragma unroll
    for (int p = 0; p < 12; p++) {
        const int icc = p / 3;
        const int dr  = p - icc * 3;

        unsigned hits = __ballot_sync(0xffffffffu, ecol[p] >= wlo && ecol[p] <= whi);
        while (hits) {                               // warp-uniform (~1-2 iters)
            const int n = __ffs(hits) - 1;
            hits &= hits - 1;
            const int   c = __shfl_sync(0xffffffffu, ecol[p], n);
            const float v = __shfl_sync(0xffffffffu, eval[p], n);
            const int rel = c - j0 + 1;              // tap center, 0..9 valid
            if ((unsigned)rel <= 9u) {
#pragma unroll
                for (int x = 0; x < 8; x++) {
                    const int dc = rel - x;
                    if ((unsigned)dc < 3u) {
#pragma unroll
                        for (int o = 0; o < 4; o++)
                            acc[o][x] = fmaf(wsm[((o * 4 + icc) * 3 + dr) * 3 + dc], v, acc[o][x]);
                    }
                }
            }
        }

        // ---- overflow fallback (support > SLOT): lane-31 slot is real ----
        if (__shfl_sync(0xffffffffu, ecol[p], 31) != SENT) {
            const int r  = i + dr - 1;
            const int gc = g * 4 + icc;
            const int cnt = g_cnt[gc * L + r];
            const float2* lst = g_list + ((size_t)gc * L + r) * (size_t)L;
            for (int n = SLOT; n < cnt; n++) {       // warp-uniform, broadcast
                const float2 e = __ldg(&lst[n]);
                const int rel = __float_as_int(e.x) - j0 + 1;
                if ((unsigned)rel <= 9u) {
                    const float v = e.y;
#pragma unroll
                    for (int x = 0; x < 8; x++) {
                        const int dc = rel - x;
                        if ((unsigned)dc < 3u) {
#pragma unroll
                            for (int o = 0; o < 4; o++)
                                acc[o][x] = fmaf(wsm[((o * 4 + icc) * 3 + dr) * 3 + dc], v, acc[o][x]);
                        }
                    }
                }
            }
        }
    }

    // ---- bias + causal mask + dense store ----
#pragma unroll
    for (int o = 0; o < 4; o++) {
        const float b = bsm[o];
        float vv[8];
#pragma unroll
        for (int x = 0; x < 8; x++)
            vv[x] = (j0 + x <= i) ? (acc[o][x] + b) : 0.0f;
        float4 v0, v1;
        v0.x=vv[0]; v0.y=vv[1]; v0.z=vv[2]; v0.w=vv[3];
        v1.x=vv[4]; v1.y=vv[5]; v1.z=vv[6]; v1.w=vv[7];
        float* ob = out + ((size_t)(g * 4 + o) * L + i) * (size_t)L + j0;
        *reinterpret_cast<float4*>(ob)     = v0;
        *reinterpret_cast<float4*>(ob + 4) = v1;
    }
}

// ---------------------------------------------------------------------------
extern "C" void kernel_launch(void* const* d_in, const int* in_sizes, int n_in,
                              void* d_out, int out_size)
{
    const float* scores = (const float*)d_in[0];
    const float* weight = (const float*)d_in[1];
    const float* bias   = (const float*)d_in[2];
    float* out = (float*)d_out;

    sparsemax_kernel<<<dim3(L, C_IN), 128>>>(scores);
    conv_sparse_kernel<<<dim3(L, GROUPS), 256>>>(weight, bias, out);
}

// round 11
// speedup vs baseline: 1.0763x; 1.0423x over previous
#include <cuda_runtime.h>
#include <cstdint>

#define L      2048
#define C_IN   16
#define GROUPS 4
#define NEG_INF -1000000000.0f
#define SLOT   32          // fixed padded slots per (ch,row); overflow -> g_list
#define SENT   0x7FFFFFFF

// Padded fast-path lists: SLOT entries per (ch,row), column-sorted, padded
// with sentinel col = INT_MAX. Always fully written for every row.
__device__ float2 g_slot[(size_t)C_IN * L * SLOT];
// Full-stride overflow lists (correctness fallback when support > SLOT).
__device__ float2 g_list[(size_t)C_IN * L * L];
__device__ int    g_cnt[C_IN * L];

// ---------------------------------------------------------------------------
// Kernel 1: row-wise sparsemax (causal) -> sorted compressed nonzero list,
// PLUS zero-fill of the output's upper triangle out[ch, row, j>row]
// (independent stores, drained under the reduction's load latency).
// One block (128 thr) per (channel,row); thread t owns cols [16t,16t+16).
// ---------------------------------------------------------------------------
__global__ __launch_bounds__(128) void sparsemax_kernel(const float* __restrict__ scores,
                                                        float* __restrict__ out)
{
    const int row  = blockIdx.x;
    const int ch   = blockIdx.y;
    const int tid  = threadIdx.x;
    const int lane = tid & 31;
    const int warp = tid >> 5;            // 4 warps
    const size_t base = ((size_t)ch * L + row) * (size_t)L;
    const int j0  = tid * 16;
    const int rem = row - j0;             // valid elements: x <= rem

    // ---- issue score loads first (latency starts now) ----
    float z[16];
    if (rem >= 15) {
#pragma unroll
        for (int q = 0; q < 4; q++) {
            const float4 a = *reinterpret_cast<const float4*>(scores + base + j0 + 4 * q);
            z[4*q+0]=a.x; z[4*q+1]=a.y; z[4*q+2]=a.z; z[4*q+3]=a.w;
        }
    } else {
#pragma unroll
        for (int x = 0; x < 16; x++)
            z[x] = (x <= rem) ? scores[base + j0 + x] : NEG_INF;
    }

    // ---- zero-fill out[ch, row, row+1 .. 2047] (fire-and-forget) ----
    {
        float* orow = out + base;             // out has identical layout
        const int s  = row + 1;
        const int sa = (s + 3) & ~3;          // first 16B-aligned col
        if (tid < sa - s) orow[s + tid] = 0.0f;      // <=3 scalar edge stores
        const float4 zq = make_float4(0.f, 0.f, 0.f, 0.f);
        for (int c = sa + 4 * tid; c < L; c += 4 * 128)
            *reinterpret_cast<float4*>(orow + c) = zq;
    }

    __shared__ float  smax[4];
    __shared__ int    swtot[4];
    __shared__ float2 slist[2048];        // survivors of tau0 (capacity-proof)

    // ---- row max ----
    float m = z[0];
#pragma unroll
    for (int k = 1; k < 16; k++) m = fmaxf(m, z[k]);
#pragma unroll
    for (int o = 16; o > 0; o >>= 1) m = fmaxf(m, __shfl_xor_sync(0xffffffffu, m, o));
    if (lane == 0) smax[warp] = m;
    __syncthreads();                                           // (1)
    const float tau0 = fmaxf(fmaxf(smax[0], smax[1]), fmaxf(smax[2], smax[3])) - 1.0f;

    // ---- compact survivors of tau0 into smem, column-sorted ----
    unsigned nz = 0u;
#pragma unroll
    for (int x = 0; x < 16; x++)
        if (z[x] > tau0) nz |= (1u << x);
    const int tcnt = __popc(nz);

    int v = tcnt;                          // warp inclusive scan
#pragma unroll
    for (int o = 1; o < 32; o <<= 1) {
        const int n = __shfl_up_sync(0xffffffffu, v, o);
        if (lane >= o) v += n;
    }
    const int toff = v - tcnt;
    if (lane == 31) swtot[warp] = v;
    __syncthreads();                                           // (2)
    int wbase = 0;
#pragma unroll
    for (int w = 0; w < 4; w++)
        if (w < warp) wbase += swtot[w];
    int pos = wbase + toff;
#pragma unroll
    for (int x = 0; x < 16; x++) {
        if ((nz >> x) & 1u) {
            slist[pos] = make_float2(__int_as_float(j0 + x), z[x]);
            pos++;
        }
    }
    __syncthreads();                                           // (3)
    if (warp != 0) return;                 // warps 1-3 done

    // ---- warp 0: Michelot on the small smem list (shfl-only) ----
    const int total = swtot[0] + swtot[1] + swtot[2] + swtot[3];
    float tau = tau0;
    int prev = -1;
    for (int it = 0; it < 32; it++) {
        float S = 0.0f, C = 0.0f;
        for (int n = lane; n < total; n += 32) {
            const float y = slist[n].y;
            if (y > tau) { S += y; C += 1.0f; }
        }
#pragma unroll
        for (int o = 16; o > 0; o >>= 1) {
            S += __shfl_xor_sync(0xffffffffu, S, o);
            C += __shfl_xor_sync(0xffffffffu, C, o);
        }
        const int ci = (int)C;             // >=1 always (argmax survives)
        tau = (S - 1.0f) / C;
        if (ci == prev) break;             // support stable -> converged
        prev = ci;
    }

    // ---- final order-preserving compaction: slots (+ overflow list) ----
    float2* slot = g_slot + (size_t)(ch * L + row) * SLOT;
    float2* lst  = g_list + base;
    int opos = 0;
    for (int n0 = 0; n0 < total; n0 += 32) {
        const int n = n0 + lane;
        float2 e; bool keep = false;
        if (n < total) { e = slist[n]; keep = (e.y > tau); }
        const unsigned b = __ballot_sync(0xffffffffu, keep);
        if (keep) {
            const int k = opos + __popc(b & ((1u << lane) - 1u));
            const float2 w = make_float2(e.x, e.y - tau);
            if (k < SLOT) slot[k] = w;
            lst[k] = w;                    // overflow-safe full copy (tiny)
        }
        opos += __popc(b);
    }
    // sentinel-pad remaining slots (col = INT_MAX)
    for (int n = opos + lane; n < SLOT; n += 32)
        slot[n] = make_float2(__int_as_float(SENT), 0.0f);
    if (lane == 0) g_cnt[ch * L + row] = opos;
}

// ---------------------------------------------------------------------------
// Kernel 2: grouped 3x3 conv from sentinel-padded sorted lists + bias,
// writing ONLY the causal (lower-triangle) part of the output; the upper
// triangle was zero-filled by kernel 1. Warps fully above the diagonal do
// nothing. One block (256 thr) per (out-row i, group g).
// ---------------------------------------------------------------------------
__global__ __launch_bounds__(256) void conv_sparse_kernel(const float* __restrict__ weight,
                                                          const float* __restrict__ bias,
                                                          float* __restrict__ out)
{
    __shared__ float wsm[144];       // [4 oc][4 ic][3][3]
    __shared__ float bsm[4];

    const int i    = blockIdx.x;     // output row
    const int g    = blockIdx.y;     // group
    const int tid  = threadIdx.x;
    const int warp = tid >> 5;
    const int lane = tid & 31;
    const int j0   = tid * 8;

    if (tid < 144) wsm[tid] = weight[g * 144 + tid];
    if (tid < 4)   bsm[tid] = bias[g * 4 + tid];

    const bool wzero = (warp * 256 > i);   // warp-uniform: all 256 cols masked

    // ---- issue all 12 list-entry loads (lane n = entry n), pre-barrier ----
    int   ecol[12];
    float eval[12];
    if (!wzero) {
#pragma unroll
        for (int p = 0; p < 12; p++) {
            const int icc = p / 3;
            const int dr  = p - icc * 3;
            const int r   = i + dr - 1;
            ecol[p] = SENT; eval[p] = 0.0f;
            if (r >= 0 && r < L) {
                const float2 e = __ldg(&g_slot[(size_t)((g * 4 + icc) * L + r) * SLOT + lane]);
                ecol[p] = __float_as_int(e.x);
                eval[p] = e.y;
            }
        }
    }
    __syncthreads();                       // weights ready

    if (wzero) return;                     // upper triangle: k1 already wrote it

    const int wlo = warp * 256 - 1;
    const int whi = warp * 256 + 256;

    float acc[4][8];
#pragma unroll
    for (int o = 0; o < 4; o++)
#pragma unroll
        for (int x = 0; x < 8; x++) acc[o][x] = 0.0f;

#pragma unroll
    for (int p = 0; p < 12; p++) {
        const int icc = p / 3;
        const int dr  = p - icc * 3;

        unsigned hits = __ballot_sync(0xffffffffu, ecol[p] >= wlo && ecol[p] <= whi);
        while (hits) {                               // warp-uniform (~1-2 iters)
            const int n = __ffs(hits) - 1;
            hits &= hits - 1;
            const int   c = __shfl_sync(0xffffffffu, ecol[p], n);
            const float v = __shfl_sync(0xffffffffu, eval[p], n);
            const int rel = c - j0 + 1;              // tap center, 0..9 valid
            if ((unsigned)rel <= 9u) {
#pragma unroll
                for (int x = 0; x < 8; x++) {
                    const int dc = rel - x;
                    if ((unsigned)dc < 3u) {
#pragma unroll
                        for (int o = 0; o < 4; o++)
                            acc[o][x] = fmaf(wsm[((o * 4 + icc) * 3 + dr) * 3 + dc], v, acc[o][x]);
                    }
                }
            }
        }

        // ---- overflow fallback (support > SLOT): lane-31 slot is real ----
        if (__shfl_sync(0xffffffffu, ecol[p], 31) != SENT) {
            const int r  = i + dr - 1;
            const int gc = g * 4 + icc;
            const int cnt = g_cnt[gc * L + r];
            const float2* lst = g_list + ((size_t)gc * L + r) * (size_t)L;
            for (int n = SLOT; n < cnt; n++) {       // warp-uniform, broadcast
                const float2 e = __ldg(&lst[n]);
                const int rel = __float_as_int(e.x) - j0 + 1;
                if ((unsigned)rel <= 9u) {
                    const float v = e.y;
#pragma unroll
                    for (int x = 0; x < 8; x++) {
                        const int dc = rel - x;
                        if ((unsigned)dc < 3u) {
#pragma unroll
                            for (int o = 0; o < 4; o++)
                                acc[o][x] = fmaf(wsm[((o * 4 + icc) * 3 + dr) * 3 + dc], v, acc[o][x]);
                        }
                    }
                }
            }
        }
    }

    // ---- bias + store (causal part only; j>i already zero from k1) ----
    if (j0 > i) return;                    // window starts beyond diagonal
    const bool full = (j0 + 7 <= i);       // fully below diagonal: no masking
#pragma unroll
    for (int o = 0; o < 4; o++) {
        const float b = bsm[o];
        float* ob = out + ((size_t)(g * 4 + o) * L + i) * (size_t)L + j0;
        if (full) {
            float4 v0, v1;
            v0.x=acc[o][0]+b; v0.y=acc[o][1]+b; v0.z=acc[o][2]+b; v0.w=acc[o][3]+b;
            v1.x=acc[o][4]+b; v1.y=acc[o][5]+b; v1.z=acc[o][6]+b; v1.w=acc[o][7]+b;
            *reinterpret_cast<float4*>(ob)     = v0;
            *reinterpret_cast<float4*>(ob + 4) = v1;
        } else {
            // diagonal-crossing window: scalar stores up to col i only
#pragma unroll
            for (int x = 0; x < 8; x++)
                if (j0 + x <= i) ob[x] = acc[o][x] + b;
        }
    }
}

// ---------------------------------------------------------------------------
extern "C" void kernel_launch(void* const* d_in, const int* in_sizes, int n_in,
                              void* d_out, int out_size)
{
    const float* scores = (const float*)d_in[0];
    const float* weight = (const float*)d_in[1];
    const float* bias   = (const float*)d_in[2];
    float* out = (float*)d_out;

    sparsemax_kernel<<<dim3(L, C_IN), 128>>>(scores, out);
    conv_sparse_kernel<<<dim3(L, GROUPS), 256>>>(weight, bias, out);
}